// round 15
// baseline (speedup 1.0000x reference)
#include <cuda_runtime.h>
#include <cuda_fp16.h>
#include <math.h>
#include <stdint.h>

// ---------------------------------------------------------------------------
// Attention_28372553957894 — R13: fused softmax.
//   S-GEMM epilogue emits per-(row, m-tile) (max, sumexp) partials.
//   reduce_stats folds 16 tiles -> per-row (M, 1/Z).
//   ATT stages P = exp(S - M) * invZ on the fly (P never hits DRAM).
// ---------------------------------------------------------------------------

#define Bsz   8
#define SEQ   2048
#define CH    256
#define MTOT  (Bsz*SEQ)

__device__ float g_S[Bsz * SEQ * SEQ];
__device__ float g_stats[(size_t)MTOT * 16 * 2];   // per (row, mtile): max, sumexp
__device__ float2 g_stat2[MTOT];                   // per row: (M, 1/Z)
__device__ __half g_xh[MTOT * CH];
__device__ __half g_Wqh[CH * CH], g_Wql[CH * CH];
__device__ __half g_Wkh[CH * CH], g_Wkl[CH * CH];
__device__ __half g_Wmh[CH * CH], g_Wml[CH * CH];
__device__ __half g_Qh[MTOT * CH], g_Ql[MTOT * CH];
__device__ __half g_Kh[MTOT * CH];
__device__ __half g_ATTh[MTOT * CH];

// ===========================================================================
// helpers
// ===========================================================================
__device__ __forceinline__ uint32_t s2u(const void* p) {
    uint32_t a;
    asm("{ .reg .u64 t; cvta.to.shared.u64 t, %1; cvt.u32.u64 %0, t; }"
        : "=r"(a) : "l"(p));
    return a;
}
__device__ __forceinline__ uint32_t swz(uint32_t o)    { return o ^ ((o >> 3) & 0x70); }  // 128B rows
__device__ __forceinline__ uint32_t swz256(uint32_t o) { return o ^ ((o >> 4) & 0x70); }  // 256B rows
__device__ __forceinline__ uint32_t swz512(uint32_t o) { return o ^ ((o >> 5) & 0x70); }  // 512B rows

__device__ __forceinline__ void cp16(uint32_t dst, const void* src) {
    asm volatile("cp.async.cg.shared.global [%0], [%1], 16;" :: "r"(dst), "l"(src));
}
__device__ __forceinline__ void cp_commit() {
    asm volatile("cp.async.commit_group;");
}
template <int N> __device__ __forceinline__ void cp_wait() {
    asm volatile("cp.async.wait_group %0;" :: "n"(N));
}

__device__ __forceinline__ void ldsm_x4(uint32_t& r0, uint32_t& r1, uint32_t& r2,
                                        uint32_t& r3, uint32_t addr) {
    asm volatile("ldmatrix.sync.aligned.m8n8.x4.shared.b16 {%0,%1,%2,%3}, [%4];"
                 : "=r"(r0), "=r"(r1), "=r"(r2), "=r"(r3) : "r"(addr));
}
__device__ __forceinline__ void ldsm_x4t(uint32_t& r0, uint32_t& r1, uint32_t& r2,
                                         uint32_t& r3, uint32_t addr) {
    asm volatile("ldmatrix.sync.aligned.m8n8.x4.trans.shared.b16 {%0,%1,%2,%3}, [%4];"
                 : "=r"(r0), "=r"(r1), "=r"(r2), "=r"(r3) : "r"(addr));
}

#define MMAH(c, a, b0v, b1v)                                                   \
    asm volatile(                                                              \
        "mma.sync.aligned.m16n8k16.row.col.f32.f16.f16.f32 "                   \
        "{%0,%1,%2,%3}, {%4,%5,%6,%7}, {%8,%9}, {%0,%1,%2,%3};"                \
        : "+f"((c)[0]), "+f"((c)[1]), "+f"((c)[2]), "+f"((c)[3])               \
        : "r"((a)[0]), "r"((a)[1]), "r"((a)[2]), "r"((a)[3]),                  \
          "r"(b0v), "r"(b1v))

__device__ __forceinline__ void split1h(float x, __half& h, __half& l) {
    h = __float2half_rn(x);
    l = __float2half_rn(x - __half2float(h));
}
__device__ __forceinline__ __half2 mkh2(__half a, __half b) {
    return __halves2half2(a, b);
}

// SMEM tile offsets for nn/s kernels (3 x 16 KB per stage)
#define SM_A_HI  0
#define SM_B_HI  16384
#define SM_B_LO  32768
#define S_BUF    49152
#define SMEM_3S_BYTES (3 * S_BUF)      // 144 KB
// fused ATT: A fp16 8 KB + B 32 KB per stage, 2 stages
#define SM1_A    0
#define SM1_B    8192
#define ATT_BUF  40960
#define SMEM_ATT_BYTES (2 * ATT_BUF)   // 80 KB

// ===========================================================================
// fp32 -> fp16 splits. x: hi only. Weights: hi + lo.
// ===========================================================================
#define NX4 (MTOT * CH / 4)
#define W4  (CH * CH / 4)
__global__ __launch_bounds__(256)
void split_all(const float* __restrict__ x,
               const float* __restrict__ Wq, const float* __restrict__ Wk,
               const float* __restrict__ Wm,
               __half* __restrict__ xh,
               __half* __restrict__ Wqh, __half* __restrict__ Wql,
               __half* __restrict__ Wkh, __half* __restrict__ Wkl,
               __half* __restrict__ Wmh, __half* __restrict__ Wml) {
    int i = blockIdx.x * 256 + threadIdx.x;
    if (i < NX4) {
        float4 v = ((const float4*)x)[i];
        __half2 hv[2] = { mkh2(__float2half_rn(v.x), __float2half_rn(v.y)),
                          mkh2(__float2half_rn(v.z), __float2half_rn(v.w)) };
        ((uint2*)xh)[i] = *(uint2*)hv;
        return;
    }
    const float* in; __half *hi, *lo; int idx;
    if (i < NX4 + W4)           { in = Wq; hi = Wqh; lo = Wql; idx = i - NX4; }
    else if (i < NX4 + 2 * W4)  { in = Wk; hi = Wkh; lo = Wkl; idx = i - NX4 - W4; }
    else if (i < NX4 + 3 * W4)  { in = Wm; hi = Wmh; lo = Wml; idx = i - NX4 - 2 * W4; }
    else return;
    float4 v = ((const float4*)in)[idx];
    __half h0,h1,h2,h3,l0,l1,l2,l3;
    split1h(v.x,h0,l0); split1h(v.y,h1,l1); split1h(v.z,h2,l2); split1h(v.w,h3,l3);
    __half2 hv[2] = { mkh2(h0,h1), mkh2(h2,h3) };
    __half2 lv[2] = { mkh2(l0,l1), mkh2(l2,l3) };
    ((uint2*)hi)[idx] = *(uint2*)hv;
    ((uint2*)lo)[idx] = *(uint2*)lv;
}

// ===========================================================================
// NN GEMM body: C = relu(A_hi @ (W_hi + W_lo) + bias)  (2-term fp16)
// ===========================================================================
__device__ __forceinline__
void gemm_nn_body(const __half* __restrict__ Ah,
                  const __half* __restrict__ Wh, const __half* __restrict__ Wl,
                  const float* __restrict__ bias,
                  float* __restrict__ Cf,
                  __half* __restrict__ Chi, __half* __restrict__ Clo,
                  int m0, int n0, int N, int K, uint32_t sb) {
    const int tid = threadIdx.x, lane = tid & 31, wid = tid >> 5;
    const int wm = (wid & 3) * 32;
    const int wn = (wid >> 2) * 64;

    float acc[2][8][4] = {};

    auto stage = [&](int kc, uint32_t bo) {
        const int k0 = kc * 64;
        #pragma unroll
        for (int i = 0; i < 4; i++) {
            int e = tid + i * 256, r = e >> 3, c = e & 7;
            size_t go = (size_t)(m0 + r) * K + k0 + c * 8;
            uint32_t so = swz((uint32_t)(r * 128 + c * 16));
            cp16(sb + bo + SM_A_HI + so, Ah + go);
        }
        #pragma unroll
        for (int i = 0; i < 4; i++) {
            int e = tid + i * 256, r = e >> 4, c = e & 15;
            size_t go = (size_t)(k0 + r) * N + n0 + c * 8;
            uint32_t so = swz256((uint32_t)(r * 256 + c * 16));
            cp16(sb + bo + SM_B_HI + so, Wh + go);
            cp16(sb + bo + SM_B_LO + so, Wl + go);
        }
    };

    stage(0, 0);           cp_commit();
    stage(1, S_BUF);       cp_commit();

    #pragma unroll
    for (int kc = 0; kc < 4; kc++) {
        if (kc == 3) cp_wait<0>(); else cp_wait<1>();
        __syncthreads();
        if (kc < 2) { stage(kc + 2, (uint32_t)(((kc + 2) % 3) * S_BUF)); cp_commit(); }
        const uint32_t bo = (uint32_t)((kc % 3) * S_BUF);

        #pragma unroll
        for (int ks = 0; ks < 4; ks++) {
            const uint32_t kb  = ks * 32;
            const uint32_t sel = (lane >> 4) << 4;
            const int kk = ks * 16;
            uint32_t ao0 = swz((uint32_t)((wm +      (lane & 15)) * 128) + kb + sel);
            uint32_t ao1 = swz((uint32_t)((wm + 16 + (lane & 15)) * 128) + kb + sel);
            uint32_t ah0[4], ah1[4];
            ldsm_x4(ah0[0],ah0[1],ah0[2],ah0[3], sb + bo + SM_A_HI + ao0);
            ldsm_x4(ah1[0],ah1[1],ah1[2],ah1[3], sb + bo + SM_A_HI + ao1);
            #pragma unroll
            for (int nq = 0; nq < 4; nq++) {
                const int brow = kk + (lane & 15);
                const int bcol = wn + nq * 16 + ((lane >> 4) << 3);
                uint32_t bof = swz256((uint32_t)(brow * 256 + bcol * 2));
                uint32_t bh[4], bl[4];
                ldsm_x4t(bh[0],bh[1],bh[2],bh[3], sb + bo + SM_B_HI + bof);
                ldsm_x4t(bl[0],bl[1],bl[2],bl[3], sb + bo + SM_B_LO + bof);
                MMAH(acc[0][nq*2  ], ah0, bh[0], bh[1]);
                MMAH(acc[0][nq*2+1], ah0, bh[2], bh[3]);
                MMAH(acc[1][nq*2  ], ah1, bh[0], bh[1]);
                MMAH(acc[1][nq*2+1], ah1, bh[2], bh[3]);
                MMAH(acc[0][nq*2  ], ah0, bl[0], bl[1]);
                MMAH(acc[0][nq*2+1], ah0, bl[2], bl[3]);
                MMAH(acc[1][nq*2  ], ah1, bl[0], bl[1]);
                MMAH(acc[1][nq*2+1], ah1, bl[2], bl[3]);
            }
        }
        if (kc < 3) __syncthreads();
    }

    #pragma unroll
    for (int mi = 0; mi < 2; mi++) {
        #pragma unroll
        for (int g = 0; g < 8; g++) {
            const int row = m0 + wm + mi * 16 + (lane >> 2);
            const int col = n0 + wn + g * 8 + (lane & 3) * 2;
            const float b0 = bias[col], b1 = bias[col + 1];
            float v00 = fmaxf(acc[mi][g][0] + b0, 0.f);
            float v01 = fmaxf(acc[mi][g][1] + b1, 0.f);
            float v10 = fmaxf(acc[mi][g][2] + b0, 0.f);
            float v11 = fmaxf(acc[mi][g][3] + b1, 0.f);
            if (Cf) {
                *(float2*)(Cf + (size_t)row * N + col)       = make_float2(v00, v01);
                *(float2*)(Cf + (size_t)(row + 8) * N + col) = make_float2(v10, v11);
            } else if (Clo) {
                __half h0,h1,l0,l1;
                split1h(v00,h0,l0); split1h(v01,h1,l1);
                *(__half2*)(Chi + (size_t)row * N + col) = mkh2(h0,h1);
                *(__half2*)(Clo + (size_t)row * N + col) = mkh2(l0,l1);
                split1h(v10,h0,l0); split1h(v11,h1,l1);
                *(__half2*)(Chi + (size_t)(row + 8) * N + col) = mkh2(h0,h1);
                *(__half2*)(Clo + (size_t)(row + 8) * N + col) = mkh2(l0,l1);
            } else {
                *(__half2*)(Chi + (size_t)row * N + col) =
                    mkh2(__float2half_rn(v00), __float2half_rn(v01));
                *(__half2*)(Chi + (size_t)(row + 8) * N + col) =
                    mkh2(__float2half_rn(v10), __float2half_rn(v11));
            }
        }
    }
}

__global__ __launch_bounds__(256)
void gemm_qk_tc(const __half* __restrict__ xh,
                const __half* __restrict__ Wqh, const __half* __restrict__ Wql,
                const __half* __restrict__ Wkh, const __half* __restrict__ Wkl,
                const float* __restrict__ bq, const float* __restrict__ bk,
                __half* __restrict__ Qh, __half* __restrict__ Ql,
                __half* __restrict__ Kh) {
    extern __shared__ char smem[];
    const uint32_t sb = s2u(smem);
    const int m0 = blockIdx.y * 128;
    const int n0 = blockIdx.x * 128;
    if (blockIdx.z == 0)
        gemm_nn_body(xh, Wqh, Wql, bq, nullptr, Qh, Ql, m0, n0, CH, CH, sb);
    else
        gemm_nn_body(xh, Wkh, Wkl, bk, nullptr, Kh, nullptr, m0, n0, CH, CH, sb);
}

__global__ __launch_bounds__(256)
void gemm_out_tc(const __half* __restrict__ Ah,
                 const __half* __restrict__ Wh, const __half* __restrict__ Wl,
                 const float* __restrict__ bias, float* __restrict__ Cf) {
    extern __shared__ char smem[];
    const uint32_t sb = s2u(smem);
    const int m0 = blockIdx.y * 128;
    const int n0 = blockIdx.x * 128;
    gemm_nn_body(Ah, Wh, Wl, bias, Cf, nullptr, nullptr, m0, n0, CH, CH, sb);
}

// ===========================================================================
// S = K_hi @ (Q_hi + Q_lo)^T per batch + per-m-tile softmax partial stats.
// ===========================================================================
__global__ __launch_bounds__(256)
void gemm_s_tc(const __half* __restrict__ Kh,
               const __half* __restrict__ Qh, const __half* __restrict__ Ql,
               float* __restrict__ Sg, float* __restrict__ stats) {
    extern __shared__ char smem[];
    const uint32_t sb = s2u(smem);
    const int tid = threadIdx.x, lane = tid & 31, wid = tid >> 5;
    const int b  = blockIdx.z;
    const int m0 = blockIdx.x * 128;
    const int n0 = blockIdx.y * 128;
    const __half* Ah = Kh + (size_t)b * SEQ * CH;
    const __half* Bh = Qh + (size_t)b * SEQ * CH;
    const __half* Bl = Ql + (size_t)b * SEQ * CH;
    float* C = Sg + (size_t)b * SEQ * SEQ;

    const int wm = (wid & 3) * 32;
    const int wn = (wid >> 2) * 64;

    float acc[2][8][4] = {};

    auto stage = [&](int kc, uint32_t bo) {
        const int k0 = kc * 64;
        #pragma unroll
        for (int i = 0; i < 4; i++) {
            int e = tid + i * 256, r = e >> 3, c = e & 7;
            uint32_t so = swz((uint32_t)(r * 128 + c * 16));
            size_t goA = (size_t)(n0 + r) * CH + k0 + c * 8;
            size_t goB = (size_t)(m0 + r) * CH + k0 + c * 8;
            cp16(sb + bo + SM_A_HI + so, Ah + goA);
            cp16(sb + bo + SM_B_HI + so, Bh + goB);
            cp16(sb + bo + SM_B_LO + so, Bl + goB);
        }
    };

    stage(0, 0);       cp_commit();
    stage(1, S_BUF);   cp_commit();

    #pragma unroll
    for (int kc = 0; kc < 4; kc++) {
        if (kc == 3) cp_wait<0>(); else cp_wait<1>();
        __syncthreads();
        if (kc < 2) { stage(kc + 2, (uint32_t)(((kc + 2) % 3) * S_BUF)); cp_commit(); }
        const uint32_t bo = (uint32_t)((kc % 3) * S_BUF);

        #pragma unroll
        for (int ks = 0; ks < 4; ks++) {
            const uint32_t kb  = ks * 32;
            const uint32_t sel = (lane >> 4) << 4;
            uint32_t ao0 = swz((uint32_t)((wm +      (lane & 15)) * 128) + kb + sel);
            uint32_t ao1 = swz((uint32_t)((wm + 16 + (lane & 15)) * 128) + kb + sel);
            uint32_t ah0[4], ah1[4];
            ldsm_x4(ah0[0],ah0[1],ah0[2],ah0[3], sb + bo + SM_A_HI + ao0);
            ldsm_x4(ah1[0],ah1[1],ah1[2],ah1[3], sb + bo + SM_A_HI + ao1);
            #pragma unroll
            for (int nq = 0; nq < 4; nq++) {
                uint32_t bof = swz((uint32_t)((wn + nq * 16 + (lane & 15)) * 128) + kb + sel);
                uint32_t bh[4], bl[4];
                ldsm_x4(bh[0],bh[1],bh[2],bh[3], sb + bo + SM_B_HI + bof);
                ldsm_x4(bl[0],bl[1],bl[2],bl[3], sb + bo + SM_B_LO + bof);
                MMAH(acc[0][nq*2  ], ah0, bh[0], bh[2]);
                MMAH(acc[0][nq*2+1], ah0, bh[1], bh[3]);
                MMAH(acc[1][nq*2  ], ah1, bh[0], bh[2]);
                MMAH(acc[1][nq*2+1], ah1, bh[1], bh[3]);
                MMAH(acc[0][nq*2  ], ah0, bl[0], bl[2]);
                MMAH(acc[0][nq*2+1], ah0, bl[1], bl[3]);
                MMAH(acc[1][nq*2  ], ah1, bl[0], bl[2]);
                MMAH(acc[1][nq*2+1], ah1, bl[1], bl[3]);
            }
        }
        if (kc < 3) __syncthreads();
    }

    // ---- softmax partial stats for this 128-col m-tile ----
    // Row r (n-dim) of this tile: vals held by 2 wn-warps x 4 lanes (lane&3) x 16.
    __syncthreads();
    float* sred = (float*)smem;     // 256 floats used
    float rmax[2][2];
    #pragma unroll
    for (int mi = 0; mi < 2; mi++) {
        #pragma unroll
        for (int hf = 0; hf < 2; hf++) {
            float mx = acc[mi][0][hf * 2];
            #pragma unroll
            for (int g = 0; g < 8; g++) {
                mx = fmaxf(mx, acc[mi][g][hf * 2]);
                mx = fmaxf(mx, acc[mi][g][hf * 2 + 1]);
            }
            mx = fmaxf(mx, __shfl_xor_sync(~0u, mx, 1));
            mx = fmaxf(mx, __shfl_xor_sync(~0u, mx, 2));
            if ((lane & 3) == 0) {
                int base = ((((wid & 3) * 2 + mi) * 2 + hf) << 3) + (lane >> 2);
                sred[((wid >> 2) << 7) + base] = mx;
            }
        }
    }
    __syncthreads();
    #pragma unroll
    for (int mi = 0; mi < 2; mi++)
        #pragma unroll
        for (int hf = 0; hf < 2; hf++) {
            int base = ((((wid & 3) * 2 + mi) * 2 + hf) << 3) + (lane >> 2);
            rmax[mi][hf] = fmaxf(sred[base], sred[128 + base]);
        }
    __syncthreads();
    #pragma unroll
    for (int mi = 0; mi < 2; mi++) {
        #pragma unroll
        for (int hf = 0; hf < 2; hf++) {
            float sm = 0.f;
            #pragma unroll
            for (int g = 0; g < 8; g++) {
                sm += __expf(acc[mi][g][hf * 2]     - rmax[mi][hf]);
                sm += __expf(acc[mi][g][hf * 2 + 1] - rmax[mi][hf]);
            }
            sm += __shfl_xor_sync(~0u, sm, 1);
            sm += __shfl_xor_sync(~0u, sm, 2);
            if ((lane & 3) == 0) {
                int base = ((((wid & 3) * 2 + mi) * 2 + hf) << 3) + (lane >> 2);
                sred[((wid >> 2) << 7) + base] = sm;
            }
        }
    }
    __syncthreads();
    if ((lane & 3) == 0 && (wid >> 2) == 0) {
        #pragma unroll
        for (int mi = 0; mi < 2; mi++)
            #pragma unroll
            for (int hf = 0; hf < 2; hf++) {
                int base = ((((wid & 3) * 2 + mi) * 2 + hf) << 3) + (lane >> 2);
                float tot = sred[base] + sred[128 + base];
                int n = n0 + (wid & 3) * 32 + mi * 16 + hf * 8 + (lane >> 2);
                size_t si = (((size_t)b * SEQ + n) * 16 + blockIdx.x) * 2;
                stats[si]     = rmax[mi][hf];
                stats[si + 1] = tot;
            }
    }

    // ---- store S tile ----
    #pragma unroll
    for (int mi = 0; mi < 2; mi++) {
        #pragma unroll
        for (int g = 0; g < 8; g++) {
            const int row = n0 + wm + mi * 16 + (lane >> 2);
            const int col = m0 + wn + g * 8 + (lane & 3) * 2;
            *(float2*)(C + (size_t)row * SEQ + col)       = make_float2(acc[mi][g][0], acc[mi][g][1]);
            *(float2*)(C + (size_t)(row + 8) * SEQ + col) = make_float2(acc[mi][g][2], acc[mi][g][3]);
        }
    }
}

// ===========================================================================
// reduce 16 per-tile stats -> per-row (M, 1/Z)
// ===========================================================================
__global__ __launch_bounds__(256)
void reduce_stats(const float* __restrict__ stats, float2* __restrict__ stat2) {
    const int row = blockIdx.x * 256 + threadIdx.x;
    if (row >= MTOT) return;
    const float2* st = (const float2*)(stats) + (size_t)row * 16;
    float M = st[0].x;
    #pragma unroll
    for (int i = 1; i < 16; i++) M = fmaxf(M, st[i].x);
    float Z = 0.f;
    #pragma unroll
    for (int i = 0; i < 16; i++) Z += st[i].y * __expf(st[i].x - M);
    stat2[row] = make_float2(M, 1.f / Z);
}

// ===========================================================================
// Fused ATT: ATT[m,h] = sum_n exp(S[n,m]-M_n)*invZ_n * V[n,h]
// CTA: 64m x 256h, 512 threads (16 warps: 2 in m x 8 in h), 2-stage pipeline.
// ===========================================================================
__global__ __launch_bounds__(512)
void gemm_att_fused(const float* __restrict__ Sg, const float2* __restrict__ stat2,
                    const __half* __restrict__ Vh, __half* __restrict__ Oh) {
    extern __shared__ char smem[];
    const uint32_t sb = s2u(smem);
    const int tid = threadIdx.x, lane = tid & 31, wid = tid >> 5;
    const int b  = blockIdx.z;
    const int m0 = blockIdx.x * 64;
    const float*  S  = Sg + (size_t)b * SEQ * SEQ;
    const float2* ST = stat2 + (size_t)b * SEQ;
    const __half* V  = Vh + (size_t)b * SEQ * CH;
    __half* O = Oh + (size_t)b * SEQ * CH;

    const int wmi = (wid & 1) * 32;   // m offset of warp
    const int wni = (wid >> 1) * 32;  // h offset of warp

    float acc[2][4][4] = {};

    // A prefetch registers: 2 float4 (S values) + 2 float2 (row stats)
    float4 pre[2];
    float2 pst[2];
    int    prow[2];

    auto ldgA = [&](int kc) {
        const int nb = kc * 64;
        #pragma unroll
        for (int i = 0; i < 2; i++) {
            int e = tid + i * 512, r = e >> 4, c4 = e & 15;
            pre[i] = *(const float4*)(S + (size_t)(nb + r) * SEQ + m0 + c4 * 4);
            pst[i] = ST[nb + r];
            prow[i] = e;     // encodes (r, c4)
        }
    };
    auto stsA = [&](uint32_t bo) {
        #pragma unroll
        for (int i = 0; i < 2; i++) {
            int e = prow[i], r = e >> 4, c4 = e & 15;
            float M = pst[i].x, iz = pst[i].y;
            __half2 p0 = mkh2(__float2half_rn(__expf(pre[i].x - M) * iz),
                              __float2half_rn(__expf(pre[i].y - M) * iz));
            __half2 p1 = mkh2(__float2half_rn(__expf(pre[i].z - M) * iz),
                              __float2half_rn(__expf(pre[i].w - M) * iz));
            uint2 pk = { *(uint32_t*)&p0, *(uint32_t*)&p1 };
            *(uint2*)(smem + bo + SM1_A + swz((uint32_t)(r * 128 + c4 * 8))) = pk;
        }
    };
    auto stageB = [&](int kc, uint32_t bo) {
        const int nb = kc * 64;
        #pragma unroll
        for (int i = 0; i < 4; i++) {
            int e = tid + i * 512, r = e >> 5, c = e & 31;
            size_t go = (size_t)(nb + r) * CH + c * 8;
            cp16(sb + bo + SM1_B + swz512((uint32_t)(r * 512 + c * 16)), V + go);
        }
    };

    ldgA(0);
    stageB(0, 0);
    cp_commit();

    #pragma unroll 1
    for (int kc = 0; kc < 32; kc++) {
        const uint32_t bo = (uint32_t)((kc & 1) * ATT_BUF);
        stsA(bo);
        cp_wait<0>();
        __syncthreads();
        if (kc < 31) {
            ldgA(kc + 1);
            stageB(kc + 1, (uint32_t)(((kc + 1) & 1) * ATT_BUF));
            cp_commit();
        }

        #pragma unroll
        for (int ks = 0; ks < 4; ks++) {
            const int kk = ks * 16;
            uint32_t ah0[4], ah1[4];
            {
                const int arow = kk + ((lane >> 4) << 3) + (lane & 7);
                const int ac0 = wmi + (((lane >> 3) & 1) << 3);
                const int ac1 = ac0 + 16;
                ldsm_x4t(ah0[0],ah0[1],ah0[2],ah0[3],
                         sb + bo + SM1_A + swz((uint32_t)(arow * 128 + ac0 * 2)));
                ldsm_x4t(ah1[0],ah1[1],ah1[2],ah1[3],
                         sb + bo + SM1_A + swz((uint32_t)(arow * 128 + ac1 * 2)));
            }
            #pragma unroll
            for (int nq = 0; nq < 2; nq++) {
                const int brow = kk + (lane & 15);
                const int bcol = wni + nq * 16 + ((lane >> 4) << 3);
                uint32_t bof = swz512((uint32_t)(brow * 512 + bcol * 2));
                uint32_t bh[4];
                ldsm_x4t(bh[0],bh[1],bh[2],bh[3], sb + bo + SM1_B + bof);
                MMAH(acc[0][nq*2  ], ah0, bh[0], bh[1]);
                MMAH(acc[0][nq*2+1], ah0, bh[2], bh[3]);
                MMAH(acc[1][nq*2  ], ah1, bh[0], bh[1]);
                MMAH(acc[1][nq*2+1], ah1, bh[2], bh[3]);
            }
        }
        // no trailing barrier needed: next stsA/stageB target the other buffer
    }

    #pragma unroll
    for (int mi = 0; mi < 2; mi++) {
        #pragma unroll
        for (int g = 0; g < 4; g++) {
            const int row = m0 + wmi + mi * 16 + (lane >> 2);
            const int col = wni + g * 8 + (lane & 3) * 2;
            *(__half2*)(O + (size_t)row * CH + col) =
                mkh2(__float2half_rn(acc[mi][g][0]), __float2half_rn(acc[mi][g][1]));
            *(__half2*)(O + (size_t)(row + 8) * CH + col) =
                mkh2(__float2half_rn(acc[mi][g][2]), __float2half_rn(acc[mi][g][3]));
        }
    }
}

// ===========================================================================
extern "C" void kernel_launch(void* const* d_in, const int* in_sizes, int n_in,
                              void* d_out, int out_size) {
    const float* x  = (const float*)d_in[0];
    const float* Wq = (const float*)d_in[1];
    const float* bq = (const float*)d_in[2];
    const float* Wk = (const float*)d_in[3];
    const float* bk = (const float*)d_in[4];
    const float* Wm = (const float*)d_in[5];
    const float* bm = (const float*)d_in[6];
    float* out = (float*)d_out;

    float* S; float* stats; float2* stat2;
    __half *xh, *Wqh, *Wql, *Wkh, *Wkl, *Wmh, *Wml;
    __half *Qh, *Ql, *Kh, *ATTh;
    cudaGetSymbolAddress((void**)&S,     g_S);
    cudaGetSymbolAddress((void**)&stats, g_stats);
    cudaGetSymbolAddress((void**)&stat2, g_stat2);
    cudaGetSymbolAddress((void**)&xh,    g_xh);
    cudaGetSymbolAddress((void**)&Wqh,   g_Wqh);  cudaGetSymbolAddress((void**)&Wql, g_Wql);
    cudaGetSymbolAddress((void**)&Wkh,   g_Wkh);  cudaGetSymbolAddress((void**)&Wkl, g_Wkl);
    cudaGetSymbolAddress((void**)&Wmh,   g_Wmh);  cudaGetSymbolAddress((void**)&Wml, g_Wml);
    cudaGetSymbolAddress((void**)&Qh,    g_Qh);   cudaGetSymbolAddress((void**)&Ql,  g_Ql);
    cudaGetSymbolAddress((void**)&Kh,    g_Kh);
    cudaGetSymbolAddress((void**)&ATTh,  g_ATTh);

    static int attr_done = 0;
    if (!attr_done) {
        cudaFuncSetAttribute(gemm_s_tc,     cudaFuncAttributeMaxDynamicSharedMemorySize, SMEM_3S_BYTES);
        cudaFuncSetAttribute(gemm_att_fused,cudaFuncAttributeMaxDynamicSharedMemorySize, SMEM_ATT_BYTES);
        cudaFuncSetAttribute(gemm_qk_tc,    cudaFuncAttributeMaxDynamicSharedMemorySize, SMEM_3S_BYTES);
        cudaFuncSetAttribute(gemm_out_tc,   cudaFuncAttributeMaxDynamicSharedMemorySize, SMEM_3S_BYTES);
        attr_done = 1;
    }

    const dim3 blk(256);

    // preconvert x (hi) + weights (hi/lo)
    const int total4 = NX4 + 3 * W4;
    split_all<<<(total4 + 255) / 256, blk>>>(x, Wq, Wk, Wm, xh,
                                             Wqh, Wql, Wkh, Wkl, Wmh, Wml);

    // q+k projections
    const dim3 gqk(CH / 128, MTOT / 128, 2);
    gemm_qk_tc<<<gqk, blk, SMEM_3S_BYTES>>>(xh, Wqh, Wql, Wkh, Wkl,
                                            bq, bk, Qh, Ql, Kh);

    // S = K_hi @ (Q_hi + Q_lo)^T  (+ per-tile softmax stats)
    const dim3 g2(SEQ / 128, SEQ / 128, Bsz);
    gemm_s_tc<<<g2, blk, SMEM_3S_BYTES>>>(Kh, Qh, Ql, S, stats);

    // fold 16 tiles -> per-row (M, 1/Z)
    reduce_stats<<<MTOT / 256, blk>>>(stats, stat2);

    // fused softmax + ATT  (V = Q_hi)
    const dim3 g3(SEQ / 64, 1, Bsz);
    gemm_att_fused<<<g3, dim3(512), SMEM_ATT_BYTES>>>(S, stat2, Qh, ATTh);

    // out = relu(ATT_hi @ (Wm_hi + Wm_lo) + bm)
    const dim3 g1(CH / 128, MTOT / 128);
    gemm_out_tc<<<g1, blk, SMEM_3S_BYTES>>>(ATTh, Wmh, Wml, bm, out);
}

// round 16
// speedup vs baseline: 1.0313x; 1.0313x over previous
#include <cuda_runtime.h>
#include <cuda_fp16.h>
#include <math.h>
#include <stdint.h>

// ---------------------------------------------------------------------------
// Attention_28372553957894 — R15: R12 config, 2-stage/96KB pipelines on
// qk/S/out (2 CTAs/SM) instead of 3-stage/144KB (1 CTA/SM). ATT unchanged.
// ---------------------------------------------------------------------------

#define Bsz   8
#define SEQ   2048
#define CH    256
#define MTOT  (Bsz*SEQ)

__device__ float g_S[Bsz * SEQ * SEQ];
__device__ __half g_xh[MTOT * CH];
__device__ __half g_Wqh[CH * CH], g_Wql[CH * CH];
__device__ __half g_Wkh[CH * CH], g_Wkl[CH * CH];
__device__ __half g_Wmh[CH * CH], g_Wml[CH * CH];
__device__ __half g_Qh[MTOT * CH], g_Ql[MTOT * CH];
__device__ __half g_Kh[MTOT * CH];
__device__ __half g_Ph[(size_t)Bsz * SEQ * SEQ];
__device__ __half g_ATTh[MTOT * CH];

// ===========================================================================
// helpers
// ===========================================================================
__device__ __forceinline__ uint32_t s2u(const void* p) {
    uint32_t a;
    asm("{ .reg .u64 t; cvta.to.shared.u64 t, %1; cvt.u32.u64 %0, t; }"
        : "=r"(a) : "l"(p));
    return a;
}
__device__ __forceinline__ uint32_t swz(uint32_t o)    { return o ^ ((o >> 3) & 0x70); }
__device__ __forceinline__ uint32_t swz256(uint32_t o) { return o ^ ((o >> 4) & 0x70); }

__device__ __forceinline__ void cp16(uint32_t dst, const void* src) {
    asm volatile("cp.async.cg.shared.global [%0], [%1], 16;" :: "r"(dst), "l"(src));
}
__device__ __forceinline__ void cp_commit() {
    asm volatile("cp.async.commit_group;");
}
template <int N> __device__ __forceinline__ void cp_wait() {
    asm volatile("cp.async.wait_group %0;" :: "n"(N));
}

__device__ __forceinline__ void ldsm_x4(uint32_t& r0, uint32_t& r1, uint32_t& r2,
                                        uint32_t& r3, uint32_t addr) {
    asm volatile("ldmatrix.sync.aligned.m8n8.x4.shared.b16 {%0,%1,%2,%3}, [%4];"
                 : "=r"(r0), "=r"(r1), "=r"(r2), "=r"(r3) : "r"(addr));
}
__device__ __forceinline__ void ldsm_x4t(uint32_t& r0, uint32_t& r1, uint32_t& r2,
                                         uint32_t& r3, uint32_t addr) {
    asm volatile("ldmatrix.sync.aligned.m8n8.x4.trans.shared.b16 {%0,%1,%2,%3}, [%4];"
                 : "=r"(r0), "=r"(r1), "=r"(r2), "=r"(r3) : "r"(addr));
}

#define MMAH(c, a, b0v, b1v)                                                   \
    asm volatile(                                                              \
        "mma.sync.aligned.m16n8k16.row.col.f32.f16.f16.f32 "                   \
        "{%0,%1,%2,%3}, {%4,%5,%6,%7}, {%8,%9}, {%0,%1,%2,%3};"                \
        : "+f"((c)[0]), "+f"((c)[1]), "+f"((c)[2]), "+f"((c)[3])               \
        : "r"((a)[0]), "r"((a)[1]), "r"((a)[2]), "r"((a)[3]),                  \
          "r"(b0v), "r"(b1v))

__device__ __forceinline__ void split1h(float x, __half& h, __half& l) {
    h = __float2half_rn(x);
    l = __float2half_rn(x - __half2float(h));
}
__device__ __forceinline__ __half2 mkh2(__half a, __half b) {
    return __halves2half2(a, b);
}

// SMEM tile offsets within one buffer (3 x 16 KB: A_HI, B_HI, B_LO)
#define SM_A_HI  0
#define SM_B_HI  16384
#define SM_B_LO  32768
#define S_BUF    49152
#define SMEM_2S_BYTES (2 * S_BUF)      // 96 KB, 2 CTAs/SM
// ATT kernel buffer (2 x 16 KB tiles), 3 stages
#define SM1_A    0
#define SM1_B    16384
#define ATT_BUF  32768
#define SMEM_ATT_BYTES (3 * ATT_BUF)   // 96 KB, 2 CTAs/SM

// ===========================================================================
// fp32 -> fp16 splits. x: hi only. Weights: hi + lo.
// ===========================================================================
#define NX4 (MTOT * CH / 4)
#define W4  (CH * CH / 4)
__global__ __launch_bounds__(256)
void split_all(const float* __restrict__ x,
               const float* __restrict__ Wq, const float* __restrict__ Wk,
               const float* __restrict__ Wm,
               __half* __restrict__ xh,
               __half* __restrict__ Wqh, __half* __restrict__ Wql,
               __half* __restrict__ Wkh, __half* __restrict__ Wkl,
               __half* __restrict__ Wmh, __half* __restrict__ Wml) {
    int i = blockIdx.x * 256 + threadIdx.x;
    if (i < NX4) {
        float4 v = ((const float4*)x)[i];
        __half2 hv[2] = { mkh2(__float2half_rn(v.x), __float2half_rn(v.y)),
                          mkh2(__float2half_rn(v.z), __float2half_rn(v.w)) };
        ((uint2*)xh)[i] = *(uint2*)hv;
        return;
    }
    const float* in; __half *hi, *lo; int idx;
    if (i < NX4 + W4)           { in = Wq; hi = Wqh; lo = Wql; idx = i - NX4; }
    else if (i < NX4 + 2 * W4)  { in = Wk; hi = Wkh; lo = Wkl; idx = i - NX4 - W4; }
    else if (i < NX4 + 3 * W4)  { in = Wm; hi = Wmh; lo = Wml; idx = i - NX4 - 2 * W4; }
    else return;
    float4 v = ((const float4*)in)[idx];
    __half h0,h1,h2,h3,l0,l1,l2,l3;
    split1h(v.x,h0,l0); split1h(v.y,h1,l1); split1h(v.z,h2,l2); split1h(v.w,h3,l3);
    __half2 hv[2] = { mkh2(h0,h1), mkh2(h2,h3) };
    __half2 lv[2] = { mkh2(l0,l1), mkh2(l2,l3) };
    ((uint2*)hi)[idx] = *(uint2*)hv;
    ((uint2*)lo)[idx] = *(uint2*)lv;
}

// ===========================================================================
// NN GEMM body: C = relu(A_hi @ (W_hi + W_lo) + bias)  (2-term fp16, 2-stage)
// ===========================================================================
__device__ __forceinline__
void gemm_nn_body(const __half* __restrict__ Ah,
                  const __half* __restrict__ Wh, const __half* __restrict__ Wl,
                  const float* __restrict__ bias,
                  float* __restrict__ Cf,
                  __half* __restrict__ Chi, __half* __restrict__ Clo,
                  int m0, int n0, int N, int K, uint32_t sb) {
    const int tid = threadIdx.x, lane = tid & 31, wid = tid >> 5;
    const int wm = (wid & 3) * 32;
    const int wn = (wid >> 2) * 64;

    float acc[2][8][4] = {};

    auto stage = [&](int kc, uint32_t bo) {
        const int k0 = kc * 64;
        #pragma unroll
        for (int i = 0; i < 4; i++) {
            int e = tid + i * 256, r = e >> 3, c = e & 7;
            size_t go = (size_t)(m0 + r) * K + k0 + c * 8;
            uint32_t so = swz((uint32_t)(r * 128 + c * 16));
            cp16(sb + bo + SM_A_HI + so, Ah + go);
        }
        #pragma unroll
        for (int i = 0; i < 4; i++) {
            int e = tid + i * 256, r = e >> 4, c = e & 15;
            size_t go = (size_t)(k0 + r) * N + n0 + c * 8;
            uint32_t so = swz256((uint32_t)(r * 256 + c * 16));
            cp16(sb + bo + SM_B_HI + so, Wh + go);
            cp16(sb + bo + SM_B_LO + so, Wl + go);
        }
    };

    stage(0, 0);
    cp_commit();

    #pragma unroll
    for (int kc = 0; kc < 4; kc++) {
        if (kc < 3) { stage(kc + 1, (uint32_t)(((kc + 1) & 1) * S_BUF)); cp_commit(); }
        if (kc == 3) cp_wait<0>(); else cp_wait<1>();
        __syncthreads();
        const uint32_t bo = (uint32_t)((kc & 1) * S_BUF);

        #pragma unroll
        for (int ks = 0; ks < 4; ks++) {
            const uint32_t kb  = ks * 32;
            const uint32_t sel = (lane >> 4) << 4;
            const int kk = ks * 16;
            uint32_t ao0 = swz((uint32_t)((wm +      (lane & 15)) * 128) + kb + sel);
            uint32_t ao1 = swz((uint32_t)((wm + 16 + (lane & 15)) * 128) + kb + sel);
            uint32_t ah0[4], ah1[4];
            ldsm_x4(ah0[0],ah0[1],ah0[2],ah0[3], sb + bo + SM_A_HI + ao0);
            ldsm_x4(ah1[0],ah1[1],ah1[2],ah1[3], sb + bo + SM_A_HI + ao1);
            #pragma unroll
            for (int nq = 0; nq < 4; nq++) {
                const int brow = kk + (lane & 15);
                const int bcol = wn + nq * 16 + ((lane >> 4) << 3);
                uint32_t bof = swz256((uint32_t)(brow * 256 + bcol * 2));
                uint32_t bh[4], bl[4];
                ldsm_x4t(bh[0],bh[1],bh[2],bh[3], sb + bo + SM_B_HI + bof);
                ldsm_x4t(bl[0],bl[1],bl[2],bl[3], sb + bo + SM_B_LO + bof);
                MMAH(acc[0][nq*2  ], ah0, bh[0], bh[1]);
                MMAH(acc[0][nq*2+1], ah0, bh[2], bh[3]);
                MMAH(acc[1][nq*2  ], ah1, bh[0], bh[1]);
                MMAH(acc[1][nq*2+1], ah1, bh[2], bh[3]);
                MMAH(acc[0][nq*2  ], ah0, bl[0], bl[1]);
                MMAH(acc[0][nq*2+1], ah0, bl[2], bl[3]);
                MMAH(acc[1][nq*2  ], ah1, bl[0], bl[1]);
                MMAH(acc[1][nq*2+1], ah1, bl[2], bl[3]);
            }
        }
        if (kc < 3) __syncthreads();
    }

    #pragma unroll
    for (int mi = 0; mi < 2; mi++) {
        #pragma unroll
        for (int g = 0; g < 8; g++) {
            const int row = m0 + wm + mi * 16 + (lane >> 2);
            const int col = n0 + wn + g * 8 + (lane & 3) * 2;
            const float b0 = bias[col], b1 = bias[col + 1];
            float v00 = fmaxf(acc[mi][g][0] + b0, 0.f);
            float v01 = fmaxf(acc[mi][g][1] + b1, 0.f);
            float v10 = fmaxf(acc[mi][g][2] + b0, 0.f);
            float v11 = fmaxf(acc[mi][g][3] + b1, 0.f);
            if (Cf) {
                *(float2*)(Cf + (size_t)row * N + col)       = make_float2(v00, v01);
                *(float2*)(Cf + (size_t)(row + 8) * N + col) = make_float2(v10, v11);
            } else if (Clo) {
                __half h0,h1,l0,l1;
                split1h(v00,h0,l0); split1h(v01,h1,l1);
                *(__half2*)(Chi + (size_t)row * N + col) = mkh2(h0,h1);
                *(__half2*)(Clo + (size_t)row * N + col) = mkh2(l0,l1);
                split1h(v10,h0,l0); split1h(v11,h1,l1);
                *(__half2*)(Chi + (size_t)(row + 8) * N + col) = mkh2(h0,h1);
                *(__half2*)(Clo + (size_t)(row + 8) * N + col) = mkh2(l0,l1);
            } else {
                *(__half2*)(Chi + (size_t)row * N + col) =
                    mkh2(__float2half_rn(v00), __float2half_rn(v01));
                *(__half2*)(Chi + (size_t)(row + 8) * N + col) =
                    mkh2(__float2half_rn(v10), __float2half_rn(v11));
            }
        }
    }
}

__global__ __launch_bounds__(256)
void gemm_qk_tc(const __half* __restrict__ xh,
                const __half* __restrict__ Wqh, const __half* __restrict__ Wql,
                const __half* __restrict__ Wkh, const __half* __restrict__ Wkl,
                const float* __restrict__ bq, const float* __restrict__ bk,
                __half* __restrict__ Qh, __half* __restrict__ Ql,
                __half* __restrict__ Kh) {
    extern __shared__ char smem[];
    const uint32_t sb = s2u(smem);
    const int m0 = blockIdx.y * 128;
    const int n0 = blockIdx.x * 128;
    if (blockIdx.z == 0)
        gemm_nn_body(xh, Wqh, Wql, bq, nullptr, Qh, Ql, m0, n0, CH, CH, sb);
    else
        gemm_nn_body(xh, Wkh, Wkl, bk, nullptr, Kh, nullptr, m0, n0, CH, CH, sb);
}

__global__ __launch_bounds__(256)
void gemm_out_tc(const __half* __restrict__ Ah,
                 const __half* __restrict__ Wh, const __half* __restrict__ Wl,
                 const float* __restrict__ bias, float* __restrict__ Cf) {
    extern __shared__ char smem[];
    const uint32_t sb = s2u(smem);
    const int m0 = blockIdx.y * 128;
    const int n0 = blockIdx.x * 128;
    gemm_nn_body(Ah, Wh, Wl, bias, Cf, nullptr, nullptr, m0, n0, CH, CH, sb);
}

// ===========================================================================
// S = K_hi @ (Q_hi + Q_lo)^T per batch (2-term fp16, 2-stage, fp32 out)
// ===========================================================================
__global__ __launch_bounds__(256)
void gemm_s_tc(const __half* __restrict__ Kh,
               const __half* __restrict__ Qh, const __half* __restrict__ Ql,
               float* __restrict__ Sg) {
    extern __shared__ char smem[];
    const uint32_t sb = s2u(smem);
    const int tid = threadIdx.x, lane = tid & 31, wid = tid >> 5;
    const int b  = blockIdx.z;
    const int m0 = blockIdx.x * 128;
    const int n0 = blockIdx.y * 128;
    const __half* Ah = Kh + (size_t)b * SEQ * CH;
    const __half* Bh = Qh + (size_t)b * SEQ * CH;
    const __half* Bl = Ql + (size_t)b * SEQ * CH;
    float* C = Sg + (size_t)b * SEQ * SEQ;

    const int wm = (wid & 3) * 32;
    const int wn = (wid >> 2) * 64;

    float acc[2][8][4] = {};

    auto stage = [&](int kc, uint32_t bo) {
        const int k0 = kc * 64;
        #pragma unroll
        for (int i = 0; i < 4; i++) {
            int e = tid + i * 256, r = e >> 3, c = e & 7;
            uint32_t so = swz((uint32_t)(r * 128 + c * 16));
            size_t goA = (size_t)(n0 + r) * CH + k0 + c * 8;
            size_t goB = (size_t)(m0 + r) * CH + k0 + c * 8;
            cp16(sb + bo + SM_A_HI + so, Ah + goA);
            cp16(sb + bo + SM_B_HI + so, Bh + goB);
            cp16(sb + bo + SM_B_LO + so, Bl + goB);
        }
    };

    stage(0, 0);
    cp_commit();

    #pragma unroll
    for (int kc = 0; kc < 4; kc++) {
        if (kc < 3) { stage(kc + 1, (uint32_t)(((kc + 1) & 1) * S_BUF)); cp_commit(); }
        if (kc == 3) cp_wait<0>(); else cp_wait<1>();
        __syncthreads();
        const uint32_t bo = (uint32_t)((kc & 1) * S_BUF);

        #pragma unroll
        for (int ks = 0; ks < 4; ks++) {
            const uint32_t kb  = ks * 32;
            const uint32_t sel = (lane >> 4) << 4;
            uint32_t ao0 = swz((uint32_t)((wm +      (lane & 15)) * 128) + kb + sel);
            uint32_t ao1 = swz((uint32_t)((wm + 16 + (lane & 15)) * 128) + kb + sel);
            uint32_t ah0[4], ah1[4];
            ldsm_x4(ah0[0],ah0[1],ah0[2],ah0[3], sb + bo + SM_A_HI + ao0);
            ldsm_x4(ah1[0],ah1[1],ah1[2],ah1[3], sb + bo + SM_A_HI + ao1);
            #pragma unroll
            for (int nq = 0; nq < 4; nq++) {
                uint32_t bof = swz((uint32_t)((wn + nq * 16 + (lane & 15)) * 128) + kb + sel);
                uint32_t bh[4], bl[4];
                ldsm_x4(bh[0],bh[1],bh[2],bh[3], sb + bo + SM_B_HI + bof);
                ldsm_x4(bl[0],bl[1],bl[2],bl[3], sb + bo + SM_B_LO + bof);
                MMAH(acc[0][nq*2  ], ah0, bh[0], bh[2]);
                MMAH(acc[0][nq*2+1], ah0, bh[1], bh[3]);
                MMAH(acc[1][nq*2  ], ah1, bh[0], bh[2]);
                MMAH(acc[1][nq*2+1], ah1, bh[1], bh[3]);
                MMAH(acc[0][nq*2  ], ah0, bl[0], bl[2]);
                MMAH(acc[0][nq*2+1], ah0, bl[1], bl[3]);
                MMAH(acc[1][nq*2  ], ah1, bl[0], bl[2]);
                MMAH(acc[1][nq*2+1], ah1, bl[1], bl[3]);
            }
        }
        if (kc < 3) __syncthreads();
    }

    #pragma unroll
    for (int mi = 0; mi < 2; mi++) {
        #pragma unroll
        for (int g = 0; g < 8; g++) {
            const int row = n0 + wm + mi * 16 + (lane >> 2);
            const int col = m0 + wn + g * 8 + (lane & 3) * 2;
            *(float2*)(C + (size_t)row * SEQ + col)       = make_float2(acc[mi][g][0], acc[mi][g][1]);
            *(float2*)(C + (size_t)(row + 8) * SEQ + col) = make_float2(acc[mi][g][2], acc[mi][g][3]);
        }
    }
}

// ===========================================================================
// ATT[m,h] = sum_n P_hi[n,m] V_hi[n,h] per batch — 1-term fp16, 3-stage.
// ===========================================================================
__global__ __launch_bounds__(256)
void gemm_att_tc(const __half* __restrict__ Pph,
                 const __half* __restrict__ Vh,
                 __half* __restrict__ Oh) {
    extern __shared__ char smem[];
    const uint32_t sb = s2u(smem);
    const int tid = threadIdx.x, lane = tid & 31, wid = tid >> 5;
    const int b  = blockIdx.z;
    const int m0 = blockIdx.x * 128;
    const int h0 = blockIdx.y * 128;
    const __half* Ah = Pph + (size_t)b * SEQ * SEQ;
    const __half* Bh = Vh + (size_t)b * SEQ * CH;
    __half* Ch = Oh + (size_t)b * SEQ * CH;

    const int wm = (wid & 3) * 32;
    const int wn = (wid >> 2) * 64;

    float acc[2][8][4] = {};

    auto stage = [&](int kc, uint32_t bo) {
        const int nb = kc * 64;
        #pragma unroll
        for (int i = 0; i < 4; i++) {
            int e = tid + i * 256, r = e >> 4, c = e & 15;
            uint32_t so = swz256((uint32_t)(r * 256 + c * 16));
            size_t goA = (size_t)(nb + r) * SEQ + m0 + c * 8;
            size_t goB = (size_t)(nb + r) * CH + h0 + c * 8;
            cp16(sb + bo + SM1_A + so, Ah + goA);
            cp16(sb + bo + SM1_B + so, Bh + goB);
        }
    };

    stage(0, 0);         cp_commit();
    stage(1, ATT_BUF);   cp_commit();

    #pragma unroll 1
    for (int kc = 0; kc < 32; kc++) {
        if (kc == 31) cp_wait<0>(); else cp_wait<1>();
        __syncthreads();
        if (kc < 30) { stage(kc + 2, (uint32_t)(((kc + 2) % 3) * ATT_BUF)); cp_commit(); }
        const uint32_t bo = (uint32_t)((kc % 3) * ATT_BUF);

        #pragma unroll
        for (int ks = 0; ks < 4; ks++) {
            const int kk = ks * 16;
            uint32_t ah0[4], ah1[4];
            {
                const int arow = kk + ((lane >> 4) << 3) + (lane & 7);
                const int ac0 = wm + (((lane >> 3) & 1) << 3);
                const int ac1 = ac0 + 16;
                ldsm_x4t(ah0[0],ah0[1],ah0[2],ah0[3],
                         sb + bo + SM1_A + swz256((uint32_t)(arow * 256 + ac0 * 2)));
                ldsm_x4t(ah1[0],ah1[1],ah1[2],ah1[3],
                         sb + bo + SM1_A + swz256((uint32_t)(arow * 256 + ac1 * 2)));
            }
            #pragma unroll
            for (int nq = 0; nq < 4; nq++) {
                const int brow = kk + (lane & 15);
                const int bcol = wn + nq * 16 + ((lane >> 4) << 3);
                uint32_t bof = swz256((uint32_t)(brow * 256 + bcol * 2));
                uint32_t bh[4];
                ldsm_x4t(bh[0],bh[1],bh[2],bh[3], sb + bo + SM1_B + bof);
                MMAH(acc[0][nq*2  ], ah0, bh[0], bh[1]);
                MMAH(acc[0][nq*2+1], ah0, bh[2], bh[3]);
                MMAH(acc[1][nq*2  ], ah1, bh[0], bh[1]);
                MMAH(acc[1][nq*2+1], ah1, bh[2], bh[3]);
            }
        }
        if (kc < 31) __syncthreads();
    }

    #pragma unroll
    for (int mi = 0; mi < 2; mi++) {
        #pragma unroll
        for (int g = 0; g < 8; g++) {
            const int row = m0 + wm + mi * 16 + (lane >> 2);
            const int col = h0 + wn + g * 8 + (lane & 3) * 2;
            *(__half2*)(Ch + (size_t)row * CH + col) =
                mkh2(__float2half_rn(acc[mi][g][0]), __float2half_rn(acc[mi][g][1]));
            *(__half2*)(Ch + (size_t)(row + 8) * CH + col) =
                mkh2(__float2half_rn(acc[mi][g][2]), __float2half_rn(acc[mi][g][3]));
        }
    }
}

// ===========================================================================
// Row softmax over m; fp16 out, one 16B store per thread.
// ===========================================================================
__global__ __launch_bounds__(256)
void softmax_f16(const float* __restrict__ S, __half* __restrict__ Ph) {
    const size_t row = blockIdx.x;
    const float* p = S + row * (size_t)SEQ;
    const int tid = threadIdx.x;
    float v[8];
    {
        float4 a = *(const float4*)(p + tid * 8);
        float4 b = *(const float4*)(p + tid * 8 + 4);
        v[0]=a.x; v[1]=a.y; v[2]=a.z; v[3]=a.w;
        v[4]=b.x; v[5]=b.y; v[6]=b.z; v[7]=b.w;
    }
    float mx = v[0];
    #pragma unroll
    for (int i = 1; i < 8; i++) mx = fmaxf(mx, v[i]);
    __shared__ float red_max[8];
    __shared__ float red_sum[8];
    #pragma unroll
    for (int o = 16; o > 0; o >>= 1) mx = fmaxf(mx, __shfl_xor_sync(~0u, mx, o));
    if ((tid & 31) == 0) red_max[tid >> 5] = mx;
    __syncthreads();
    if (tid < 32) {
        float t = (tid < 8) ? red_max[tid] : -INFINITY;
        #pragma unroll
        for (int o = 4; o > 0; o >>= 1) t = fmaxf(t, __shfl_xor_sync(~0u, t, o));
        if (tid == 0) red_max[0] = t;
    }
    __syncthreads();
    mx = red_max[0];
    float s = 0.f;
    #pragma unroll
    for (int i = 0; i < 8; i++) { v[i] = __expf(v[i] - mx); s += v[i]; }
    #pragma unroll
    for (int o = 16; o > 0; o >>= 1) s += __shfl_xor_sync(~0u, s, o);
    if ((tid & 31) == 0) red_sum[tid >> 5] = s;
    __syncthreads();
    if (tid < 32) {
        float t = (tid < 8) ? red_sum[tid] : 0.f;
        #pragma unroll
        for (int o = 4; o > 0; o >>= 1) t += __shfl_xor_sync(~0u, t, o);
        if (tid == 0) red_sum[0] = t;
    }
    __syncthreads();
    const float inv = 1.f / red_sum[0];
    __half2 ov[4];
    #pragma unroll
    for (int i = 0; i < 4; i++) {
        ov[i] = mkh2(__float2half_rn(v[2*i] * inv), __float2half_rn(v[2*i+1] * inv));
    }
    *(uint4*)(Ph + row * (size_t)SEQ + tid * 8) = *(uint4*)ov;
}

// ===========================================================================
extern "C" void kernel_launch(void* const* d_in, const int* in_sizes, int n_in,
                              void* d_out, int out_size) {
    const float* x  = (const float*)d_in[0];
    const float* Wq = (const float*)d_in[1];
    const float* bq = (const float*)d_in[2];
    const float* Wk = (const float*)d_in[3];
    const float* bk = (const float*)d_in[4];
    const float* Wm = (const float*)d_in[5];
    const float* bm = (const float*)d_in[6];
    float* out = (float*)d_out;

    float* S;
    __half *xh, *Wqh, *Wql, *Wkh, *Wkl, *Wmh, *Wml;
    __half *Qh, *Ql, *Kh, *Ph, *ATTh;
    cudaGetSymbolAddress((void**)&S,    g_S);
    cudaGetSymbolAddress((void**)&xh,   g_xh);
    cudaGetSymbolAddress((void**)&Wqh,  g_Wqh);  cudaGetSymbolAddress((void**)&Wql,  g_Wql);
    cudaGetSymbolAddress((void**)&Wkh,  g_Wkh);  cudaGetSymbolAddress((void**)&Wkl,  g_Wkl);
    cudaGetSymbolAddress((void**)&Wmh,  g_Wmh);  cudaGetSymbolAddress((void**)&Wml,  g_Wml);
    cudaGetSymbolAddress((void**)&Qh,   g_Qh);   cudaGetSymbolAddress((void**)&Ql,   g_Ql);
    cudaGetSymbolAddress((void**)&Kh,   g_Kh);
    cudaGetSymbolAddress((void**)&Ph,   g_Ph);
    cudaGetSymbolAddress((void**)&ATTh, g_ATTh);

    static int attr_done = 0;
    if (!attr_done) {
        cudaFuncSetAttribute(gemm_s_tc,   cudaFuncAttributeMaxDynamicSharedMemorySize, SMEM_2S_BYTES);
        cudaFuncSetAttribute(gemm_att_tc, cudaFuncAttributeMaxDynamicSharedMemorySize, SMEM_ATT_BYTES);
        cudaFuncSetAttribute(gemm_qk_tc,  cudaFuncAttributeMaxDynamicSharedMemorySize, SMEM_2S_BYTES);
        cudaFuncSetAttribute(gemm_out_tc, cudaFuncAttributeMaxDynamicSharedMemorySize, SMEM_2S_BYTES);
        attr_done = 1;
    }

    const dim3 blk(256);

    // preconvert x (hi) + weights (hi/lo)
    const int total4 = NX4 + 3 * W4;
    split_all<<<(total4 + 255) / 256, blk>>>(x, Wq, Wk, Wm, xh,
                                             Wqh, Wql, Wkh, Wkl, Wmh, Wml);

    // q+k projections
    const dim3 gqk(CH / 128, MTOT / 128, 2);
    gemm_qk_tc<<<gqk, blk, SMEM_2S_BYTES>>>(xh, Wqh, Wql, Wkh, Wkl,
                                            bq, bk, Qh, Ql, Kh);

    // S = K_hi @ (Q_hi + Q_lo)^T
    const dim3 g2(SEQ / 128, SEQ / 128, Bsz);
    gemm_s_tc<<<g2, blk, SMEM_2S_BYTES>>>(Kh, Qh, Ql, S);

    // softmax -> P (fp16)
    softmax_f16<<<Bsz * SEQ, blk>>>(S, Ph);

    // ATT = P_hi @ V_hi  (V = Q_hi)
    const dim3 g3(SEQ / 128, CH / 128, Bsz);
    gemm_att_tc<<<g3, blk, SMEM_ATT_BYTES>>>(Ph, Qh, ATTh);

    // out = relu(ATT_hi @ (Wm_hi + Wm_lo) + bm)
    const dim3 g1(CH / 128, MTOT / 128);
    gemm_out_tc<<<g1, blk, SMEM_2S_BYTES>>>(ATTh, Wmh, Wml, bm, out);
}

// round 17
// speedup vs baseline: 1.0598x; 1.0276x over previous
#include <cuda_runtime.h>
#include <cuda_fp16.h>
#include <math.h>
#include <stdint.h>

// ---------------------------------------------------------------------------
// Attention_28372553957894 — R16: R15 + S stored fp16 relative to per-tile
// row max (halves softmax traffic; no max pass in softmax).
// ---------------------------------------------------------------------------

#define Bsz   8
#define SEQ   2048
#define CH    256
#define MTOT  (Bsz*SEQ)

__device__ __half g_Sh[(size_t)Bsz * SEQ * SEQ];   // s - tilemax, fp16
__device__ float  g_tmax[(size_t)MTOT * 16];       // per (row, m-tile) max
__device__ __half g_xh[MTOT * CH];
__device__ __half g_Wqh[CH * CH], g_Wql[CH * CH];
__device__ __half g_Wkh[CH * CH], g_Wkl[CH * CH];
__device__ __half g_Wmh[CH * CH], g_Wml[CH * CH];
__device__ __half g_Qh[MTOT * CH], g_Ql[MTOT * CH];
__device__ __half g_Kh[MTOT * CH];
__device__ __half g_Ph[(size_t)Bsz * SEQ * SEQ];
__device__ __half g_ATTh[MTOT * CH];

// ===========================================================================
// helpers
// ===========================================================================
__device__ __forceinline__ uint32_t s2u(const void* p) {
    uint32_t a;
    asm("{ .reg .u64 t; cvta.to.shared.u64 t, %1; cvt.u32.u64 %0, t; }"
        : "=r"(a) : "l"(p));
    return a;
}
__device__ __forceinline__ uint32_t swz(uint32_t o)    { return o ^ ((o >> 3) & 0x70); }
__device__ __forceinline__ uint32_t swz256(uint32_t o) { return o ^ ((o >> 4) & 0x70); }

__device__ __forceinline__ void cp16(uint32_t dst, const void* src) {
    asm volatile("cp.async.cg.shared.global [%0], [%1], 16;" :: "r"(dst), "l"(src));
}
__device__ __forceinline__ void cp_commit() {
    asm volatile("cp.async.commit_group;");
}
template <int N> __device__ __forceinline__ void cp_wait() {
    asm volatile("cp.async.wait_group %0;" :: "n"(N));
}

__device__ __forceinline__ void ldsm_x4(uint32_t& r0, uint32_t& r1, uint32_t& r2,
                                        uint32_t& r3, uint32_t addr) {
    asm volatile("ldmatrix.sync.aligned.m8n8.x4.shared.b16 {%0,%1,%2,%3}, [%4];"
                 : "=r"(r0), "=r"(r1), "=r"(r2), "=r"(r3) : "r"(addr));
}
__device__ __forceinline__ void ldsm_x4t(uint32_t& r0, uint32_t& r1, uint32_t& r2,
                                         uint32_t& r3, uint32_t addr) {
    asm volatile("ldmatrix.sync.aligned.m8n8.x4.trans.shared.b16 {%0,%1,%2,%3}, [%4];"
                 : "=r"(r0), "=r"(r1), "=r"(r2), "=r"(r3) : "r"(addr));
}

#define MMAH(c, a, b0v, b1v)                                                   \
    asm volatile(                                                              \
        "mma.sync.aligned.m16n8k16.row.col.f32.f16.f16.f32 "                   \
        "{%0,%1,%2,%3}, {%4,%5,%6,%7}, {%8,%9}, {%0,%1,%2,%3};"                \
        : "+f"((c)[0]), "+f"((c)[1]), "+f"((c)[2]), "+f"((c)[3])               \
        : "r"((a)[0]), "r"((a)[1]), "r"((a)[2]), "r"((a)[3]),                  \
          "r"(b0v), "r"(b1v))

__device__ __forceinline__ void split1h(float x, __half& h, __half& l) {
    h = __float2half_rn(x);
    l = __float2half_rn(x - __half2float(h));
}
__device__ __forceinline__ __half2 mkh2(__half a, __half b) {
    return __halves2half2(a, b);
}

// SMEM tile offsets within one buffer (3 x 16 KB: A_HI, B_HI, B_LO)
#define SM_A_HI  0
#define SM_B_HI  16384
#define SM_B_LO  32768
#define S_BUF    49152
#define SMEM_2S_BYTES (2 * S_BUF)      // 96 KB, 2 CTAs/SM
// ATT kernel buffer (2 x 16 KB tiles), 3 stages
#define SM1_A    0
#define SM1_B    16384
#define ATT_BUF  32768
#define SMEM_ATT_BYTES (3 * ATT_BUF)   // 96 KB, 2 CTAs/SM

// ===========================================================================
// fp32 -> fp16 splits. x: hi only. Weights: hi + lo.
// ===========================================================================
#define NX4 (MTOT * CH / 4)
#define W4  (CH * CH / 4)
__global__ __launch_bounds__(256)
void split_all(const float* __restrict__ x,
               const float* __restrict__ Wq, const float* __restrict__ Wk,
               const float* __restrict__ Wm,
               __half* __restrict__ xh,
               __half* __restrict__ Wqh, __half* __restrict__ Wql,
               __half* __restrict__ Wkh, __half* __restrict__ Wkl,
               __half* __restrict__ Wmh, __half* __restrict__ Wml) {
    int i = blockIdx.x * 256 + threadIdx.x;
    if (i < NX4) {
        float4 v = ((const float4*)x)[i];
        __half2 hv[2] = { mkh2(__float2half_rn(v.x), __float2half_rn(v.y)),
                          mkh2(__float2half_rn(v.z), __float2half_rn(v.w)) };
        ((uint2*)xh)[i] = *(uint2*)hv;
        return;
    }
    const float* in; __half *hi, *lo; int idx;
    if (i < NX4 + W4)           { in = Wq; hi = Wqh; lo = Wql; idx = i - NX4; }
    else if (i < NX4 + 2 * W4)  { in = Wk; hi = Wkh; lo = Wkl; idx = i - NX4 - W4; }
    else if (i < NX4 + 3 * W4)  { in = Wm; hi = Wmh; lo = Wml; idx = i - NX4 - 2 * W4; }
    else return;
    float4 v = ((const float4*)in)[idx];
    __half h0,h1,h2,h3,l0,l1,l2,l3;
    split1h(v.x,h0,l0); split1h(v.y,h1,l1); split1h(v.z,h2,l2); split1h(v.w,h3,l3);
    __half2 hv[2] = { mkh2(h0,h1), mkh2(h2,h3) };
    __half2 lv[2] = { mkh2(l0,l1), mkh2(l2,l3) };
    ((uint2*)hi)[idx] = *(uint2*)hv;
    ((uint2*)lo)[idx] = *(uint2*)lv;
}

// ===========================================================================
// NN GEMM body: C = relu(A_hi @ (W_hi + W_lo) + bias)  (2-term fp16, 2-stage)
// ===========================================================================
__device__ __forceinline__
void gemm_nn_body(const __half* __restrict__ Ah,
                  const __half* __restrict__ Wh, const __half* __restrict__ Wl,
                  const float* __restrict__ bias,
                  float* __restrict__ Cf,
                  __half* __restrict__ Chi, __half* __restrict__ Clo,
                  int m0, int n0, int N, int K, uint32_t sb) {
    const int tid = threadIdx.x, lane = tid & 31, wid = tid >> 5;
    const int wm = (wid & 3) * 32;
    const int wn = (wid >> 2) * 64;

    float acc[2][8][4] = {};

    auto stage = [&](int kc, uint32_t bo) {
        const int k0 = kc * 64;
        #pragma unroll
        for (int i = 0; i < 4; i++) {
            int e = tid + i * 256, r = e >> 3, c = e & 7;
            size_t go = (size_t)(m0 + r) * K + k0 + c * 8;
            uint32_t so = swz((uint32_t)(r * 128 + c * 16));
            cp16(sb + bo + SM_A_HI + so, Ah + go);
        }
        #pragma unroll
        for (int i = 0; i < 4; i++) {
            int e = tid + i * 256, r = e >> 4, c = e & 15;
            size_t go = (size_t)(k0 + r) * N + n0 + c * 8;
            uint32_t so = swz256((uint32_t)(r * 256 + c * 16));
            cp16(sb + bo + SM_B_HI + so, Wh + go);
            cp16(sb + bo + SM_B_LO + so, Wl + go);
        }
    };

    stage(0, 0);
    cp_commit();

    #pragma unroll
    for (int kc = 0; kc < 4; kc++) {
        if (kc < 3) { stage(kc + 1, (uint32_t)(((kc + 1) & 1) * S_BUF)); cp_commit(); }
        if (kc == 3) cp_wait<0>(); else cp_wait<1>();
        __syncthreads();
        const uint32_t bo = (uint32_t)((kc & 1) * S_BUF);

        #pragma unroll
        for (int ks = 0; ks < 4; ks++) {
            const uint32_t kb  = ks * 32;
            const uint32_t sel = (lane >> 4) << 4;
            const int kk = ks * 16;
            uint32_t ao0 = swz((uint32_t)((wm +      (lane & 15)) * 128) + kb + sel);
            uint32_t ao1 = swz((uint32_t)((wm + 16 + (lane & 15)) * 128) + kb + sel);
            uint32_t ah0[4], ah1[4];
            ldsm_x4(ah0[0],ah0[1],ah0[2],ah0[3], sb + bo + SM_A_HI + ao0);
            ldsm_x4(ah1[0],ah1[1],ah1[2],ah1[3], sb + bo + SM_A_HI + ao1);
            #pragma unroll
            for (int nq = 0; nq < 4; nq++) {
                const int brow = kk + (lane & 15);
                const int bcol = wn + nq * 16 + ((lane >> 4) << 3);
                uint32_t bof = swz256((uint32_t)(brow * 256 + bcol * 2));
                uint32_t bh[4], bl[4];
                ldsm_x4t(bh[0],bh[1],bh[2],bh[3], sb + bo + SM_B_HI + bof);
                ldsm_x4t(bl[0],bl[1],bl[2],bl[3], sb + bo + SM_B_LO + bof);
                MMAH(acc[0][nq*2  ], ah0, bh[0], bh[1]);
                MMAH(acc[0][nq*2+1], ah0, bh[2], bh[3]);
                MMAH(acc[1][nq*2  ], ah1, bh[0], bh[1]);
                MMAH(acc[1][nq*2+1], ah1, bh[2], bh[3]);
                MMAH(acc[0][nq*2  ], ah0, bl[0], bl[1]);
                MMAH(acc[0][nq*2+1], ah0, bl[2], bl[3]);
                MMAH(acc[1][nq*2  ], ah1, bl[0], bl[1]);
                MMAH(acc[1][nq*2+1], ah1, bl[2], bl[3]);
            }
        }
        if (kc < 3) __syncthreads();
    }

    #pragma unroll
    for (int mi = 0; mi < 2; mi++) {
        #pragma unroll
        for (int g = 0; g < 8; g++) {
            const int row = m0 + wm + mi * 16 + (lane >> 2);
            const int col = n0 + wn + g * 8 + (lane & 3) * 2;
            const float b0 = bias[col], b1 = bias[col + 1];
            float v00 = fmaxf(acc[mi][g][0] + b0, 0.f);
            float v01 = fmaxf(acc[mi][g][1] + b1, 0.f);
            float v10 = fmaxf(acc[mi][g][2] + b0, 0.f);
            float v11 = fmaxf(acc[mi][g][3] + b1, 0.f);
            if (Cf) {
                *(float2*)(Cf + (size_t)row * N + col)       = make_float2(v00, v01);
                *(float2*)(Cf + (size_t)(row + 8) * N + col) = make_float2(v10, v11);
            } else if (Clo) {
                __half h0,h1,l0,l1;
                split1h(v00,h0,l0); split1h(v01,h1,l1);
                *(__half2*)(Chi + (size_t)row * N + col) = mkh2(h0,h1);
                *(__half2*)(Clo + (size_t)row * N + col) = mkh2(l0,l1);
                split1h(v10,h0,l0); split1h(v11,h1,l1);
                *(__half2*)(Chi + (size_t)(row + 8) * N + col) = mkh2(h0,h1);
                *(__half2*)(Clo + (size_t)(row + 8) * N + col) = mkh2(l0,l1);
            } else {
                *(__half2*)(Chi + (size_t)row * N + col) =
                    mkh2(__float2half_rn(v00), __float2half_rn(v01));
                *(__half2*)(Chi + (size_t)(row + 8) * N + col) =
                    mkh2(__float2half_rn(v10), __float2half_rn(v11));
            }
        }
    }
}

__global__ __launch_bounds__(256)
void gemm_qk_tc(const __half* __restrict__ xh,
                const __half* __restrict__ Wqh, const __half* __restrict__ Wql,
                const __half* __restrict__ Wkh, const __half* __restrict__ Wkl,
                const float* __restrict__ bq, const float* __restrict__ bk,
                __half* __restrict__ Qh, __half* __restrict__ Ql,
                __half* __restrict__ Kh) {
    extern __shared__ char smem[];
    const uint32_t sb = s2u(smem);
    const int m0 = blockIdx.y * 128;
    const int n0 = blockIdx.x * 128;
    if (blockIdx.z == 0)
        gemm_nn_body(xh, Wqh, Wql, bq, nullptr, Qh, Ql, m0, n0, CH, CH, sb);
    else
        gemm_nn_body(xh, Wkh, Wkl, bk, nullptr, Kh, nullptr, m0, n0, CH, CH, sb);
}

__global__ __launch_bounds__(256)
void gemm_out_tc(const __half* __restrict__ Ah,
                 const __half* __restrict__ Wh, const __half* __restrict__ Wl,
                 const float* __restrict__ bias, float* __restrict__ Cf) {
    extern __shared__ char smem[];
    const uint32_t sb = s2u(smem);
    const int m0 = blockIdx.y * 128;
    const int n0 = blockIdx.x * 128;
    gemm_nn_body(Ah, Wh, Wl, bias, Cf, nullptr, nullptr, m0, n0, CH, CH, sb);
}

// ===========================================================================
// S = K_hi @ (Q_hi + Q_lo)^T per batch; stores fp16 (s - tilemax) + tilemax.
// ===========================================================================
__global__ __launch_bounds__(256)
void gemm_s_tc(const __half* __restrict__ Kh,
               const __half* __restrict__ Qh, const __half* __restrict__ Ql,
               __half* __restrict__ Sh, float* __restrict__ tmax) {
    extern __shared__ char smem[];
    const uint32_t sb = s2u(smem);
    const int tid = threadIdx.x, lane = tid & 31, wid = tid >> 5;
    const int b  = blockIdx.z;
    const int m0 = blockIdx.x * 128;
    const int n0 = blockIdx.y * 128;
    const __half* Ah = Kh + (size_t)b * SEQ * CH;
    const __half* Bh = Qh + (size_t)b * SEQ * CH;
    const __half* Bl = Ql + (size_t)b * SEQ * CH;
    __half* C = Sh + (size_t)b * SEQ * SEQ;

    const int wm = (wid & 3) * 32;
    const int wn = (wid >> 2) * 64;

    float acc[2][8][4] = {};

    auto stage = [&](int kc, uint32_t bo) {
        const int k0 = kc * 64;
        #pragma unroll
        for (int i = 0; i < 4; i++) {
            int e = tid + i * 256, r = e >> 3, c = e & 7;
            uint32_t so = swz((uint32_t)(r * 128 + c * 16));
            size_t goA = (size_t)(n0 + r) * CH + k0 + c * 8;
            size_t goB = (size_t)(m0 + r) * CH + k0 + c * 8;
            cp16(sb + bo + SM_A_HI + so, Ah + goA);
            cp16(sb + bo + SM_B_HI + so, Bh + goB);
            cp16(sb + bo + SM_B_LO + so, Bl + goB);
        }
    };

    stage(0, 0);
    cp_commit();

    #pragma unroll
    for (int kc = 0; kc < 4; kc++) {
        if (kc < 3) { stage(kc + 1, (uint32_t)(((kc + 1) & 1) * S_BUF)); cp_commit(); }
        if (kc == 3) cp_wait<0>(); else cp_wait<1>();
        __syncthreads();
        const uint32_t bo = (uint32_t)((kc & 1) * S_BUF);

        #pragma unroll
        for (int ks = 0; ks < 4; ks++) {
            const uint32_t kb  = ks * 32;
            const uint32_t sel = (lane >> 4) << 4;
            uint32_t ao0 = swz((uint32_t)((wm +      (lane & 15)) * 128) + kb + sel);
            uint32_t ao1 = swz((uint32_t)((wm + 16 + (lane & 15)) * 128) + kb + sel);
            uint32_t ah0[4], ah1[4];
            ldsm_x4(ah0[0],ah0[1],ah0[2],ah0[3], sb + bo + SM_A_HI + ao0);
            ldsm_x4(ah1[0],ah1[1],ah1[2],ah1[3], sb + bo + SM_A_HI + ao1);
            #pragma unroll
            for (int nq = 0; nq < 4; nq++) {
                uint32_t bof = swz((uint32_t)((wn + nq * 16 + (lane & 15)) * 128) + kb + sel);
                uint32_t bh[4], bl[4];
                ldsm_x4(bh[0],bh[1],bh[2],bh[3], sb + bo + SM_B_HI + bof);
                ldsm_x4(bl[0],bl[1],bl[2],bl[3], sb + bo + SM_B_LO + bof);
                MMAH(acc[0][nq*2  ], ah0, bh[0], bh[2]);
                MMAH(acc[0][nq*2+1], ah0, bh[1], bh[3]);
                MMAH(acc[1][nq*2  ], ah1, bh[0], bh[2]);
                MMAH(acc[1][nq*2+1], ah1, bh[1], bh[3]);
                MMAH(acc[0][nq*2  ], ah0, bl[0], bl[2]);
                MMAH(acc[0][nq*2+1], ah0, bl[1], bl[3]);
                MMAH(acc[1][nq*2  ], ah1, bl[0], bl[2]);
                MMAH(acc[1][nq*2+1], ah1, bl[1], bl[3]);
            }
        }
        if (kc < 3) __syncthreads();
    }

    // ---- per-row tile max (validated mapping from R13) ----
    __syncthreads();
    float* sred = (float*)smem;     // 256 floats
    float rmax[2][2];
    #pragma unroll
    for (int mi = 0; mi < 2; mi++) {
        #pragma unroll
        for (int hf = 0; hf < 2; hf++) {
            float mx = acc[mi][0][hf * 2];
            #pragma unroll
            for (int g = 0; g < 8; g++) {
                mx = fmaxf(mx, acc[mi][g][hf * 2]);
                mx = fmaxf(mx, acc[mi][g][hf * 2 + 1]);
            }
            mx = fmaxf(mx, __shfl_xor_sync(~0u, mx, 1));
            mx = fmaxf(mx, __shfl_xor_sync(~0u, mx, 2));
            if ((lane & 3) == 0) {
                int base = ((((wid & 3) * 2 + mi) * 2 + hf) << 3) + (lane >> 2);
                sred[((wid >> 2) << 7) + base] = mx;
            }
        }
    }
    __syncthreads();
    #pragma unroll
    for (int mi = 0; mi < 2; mi++)
        #pragma unroll
        for (int hf = 0; hf < 2; hf++) {
            int base = ((((wid & 3) * 2 + mi) * 2 + hf) << 3) + (lane >> 2);
            rmax[mi][hf] = fmaxf(sred[base], sred[128 + base]);
        }
    if ((lane & 3) == 0 && (wid >> 2) == 0) {
        #pragma unroll
        for (int mi = 0; mi < 2; mi++)
            #pragma unroll
            for (int hf = 0; hf < 2; hf++) {
                int n = n0 + (wid & 3) * 32 + mi * 16 + hf * 8 + (lane >> 2);
                tmax[(((size_t)b * SEQ + n) << 4) + blockIdx.x] = rmax[mi][hf];
            }
    }

    // ---- store fp16 (s - tilemax) ----
    #pragma unroll
    for (int mi = 0; mi < 2; mi++) {
        #pragma unroll
        for (int g = 0; g < 8; g++) {
            const int row = n0 + wm + mi * 16 + (lane >> 2);
            const int col = m0 + wn + g * 8 + (lane & 3) * 2;
            *(__half2*)(C + (size_t)row * SEQ + col) =
                mkh2(__float2half_rn(acc[mi][g][0] - rmax[mi][0]),
                     __float2half_rn(acc[mi][g][1] - rmax[mi][0]));
            *(__half2*)(C + (size_t)(row + 8) * SEQ + col) =
                mkh2(__float2half_rn(acc[mi][g][2] - rmax[mi][1]),
                     __float2half_rn(acc[mi][g][3] - rmax[mi][1]));
        }
    }
}

// ===========================================================================
// ATT[m,h] = sum_n P_hi[n,m] V_hi[n,h] per batch — 1-term fp16, 3-stage.
// ===========================================================================
__global__ __launch_bounds__(256)
void gemm_att_tc(const __half* __restrict__ Pph,
                 const __half* __restrict__ Vh,
                 __half* __restrict__ Oh) {
    extern __shared__ char smem[];
    const uint32_t sb = s2u(smem);
    const int tid = threadIdx.x, lane = tid & 31, wid = tid >> 5;
    const int b  = blockIdx.z;
    const int m0 = blockIdx.x * 128;
    const int h0 = blockIdx.y * 128;
    const __half* Ah = Pph + (size_t)b * SEQ * SEQ;
    const __half* Bh = Vh + (size_t)b * SEQ * CH;
    __half* Ch = Oh + (size_t)b * SEQ * CH;

    const int wm = (wid & 3) * 32;
    const int wn = (wid >> 2) * 64;

    float acc[2][8][4] = {};

    auto stage = [&](int kc, uint32_t bo) {
        const int nb = kc * 64;
        #pragma unroll
        for (int i = 0; i < 4; i++) {
            int e = tid + i * 256, r = e >> 4, c = e & 15;
            uint32_t so = swz256((uint32_t)(r * 256 + c * 16));
            size_t goA = (size_t)(nb + r) * SEQ + m0 + c * 8;
            size_t goB = (size_t)(nb + r) * CH + h0 + c * 8;
            cp16(sb + bo + SM1_A + so, Ah + goA);
            cp16(sb + bo + SM1_B + so, Bh + goB);
        }
    };

    stage(0, 0);         cp_commit();
    stage(1, ATT_BUF);   cp_commit();

    #pragma unroll 1
    for (int kc = 0; kc < 32; kc++) {
        if (kc == 31) cp_wait<0>(); else cp_wait<1>();
        __syncthreads();
        if (kc < 30) { stage(kc + 2, (uint32_t)(((kc + 2) % 3) * ATT_BUF)); cp_commit(); }
        const uint32_t bo = (uint32_t)((kc % 3) * ATT_BUF);

        #pragma unroll
        for (int ks = 0; ks < 4; ks++) {
            const int kk = ks * 16;
            uint32_t ah0[4], ah1[4];
            {
                const int arow = kk + ((lane >> 4) << 3) + (lane & 7);
                const int ac0 = wm + (((lane >> 3) & 1) << 3);
                const int ac1 = ac0 + 16;
                ldsm_x4t(ah0[0],ah0[1],ah0[2],ah0[3],
                         sb + bo + SM1_A + swz256((uint32_t)(arow * 256 + ac0 * 2)));
                ldsm_x4t(ah1[0],ah1[1],ah1[2],ah1[3],
                         sb + bo + SM1_A + swz256((uint32_t)(arow * 256 + ac1 * 2)));
            }
            #pragma unroll
            for (int nq = 0; nq < 4; nq++) {
                const int brow = kk + (lane & 15);
                const int bcol = wn + nq * 16 + ((lane >> 4) << 3);
                uint32_t bof = swz256((uint32_t)(brow * 256 + bcol * 2));
                uint32_t bh[4];
                ldsm_x4t(bh[0],bh[1],bh[2],bh[3], sb + bo + SM1_B + bof);
                MMAH(acc[0][nq*2  ], ah0, bh[0], bh[1]);
                MMAH(acc[0][nq*2+1], ah0, bh[2], bh[3]);
                MMAH(acc[1][nq*2  ], ah1, bh[0], bh[1]);
                MMAH(acc[1][nq*2+1], ah1, bh[2], bh[3]);
            }
        }
        if (kc < 31) __syncthreads();
    }

    #pragma unroll
    for (int mi = 0; mi < 2; mi++) {
        #pragma unroll
        for (int g = 0; g < 8; g++) {
            const int row = m0 + wm + mi * 16 + (lane >> 2);
            const int col = h0 + wn + g * 8 + (lane & 3) * 2;
            *(__half2*)(Ch + (size_t)row * CH + col) =
                mkh2(__float2half_rn(acc[mi][g][0]), __float2half_rn(acc[mi][g][1]));
            *(__half2*)(Ch + (size_t)(row + 8) * CH + col) =
                mkh2(__float2half_rn(acc[mi][g][2]), __float2half_rn(acc[mi][g][3]));
        }
    }
}

// ===========================================================================
// Softmax from fp16 (s - tilemax) + 16 tile maxes; no max pass needed.
// ===========================================================================
__global__ __launch_bounds__(256)
void softmax_f16(const __half* __restrict__ Sh, const float* __restrict__ tmax,
                 __half* __restrict__ Ph) {
    const size_t row = blockIdx.x;
    const int tid = threadIdx.x;
    __shared__ float tm[16];
    __shared__ float red_sum[8];
    if (tid < 16) tm[tid] = tmax[(row << 4) + tid];
    __syncthreads();
    float M = tm[0];
    #pragma unroll
    for (int i = 1; i < 16; i++) M = fmaxf(M, tm[i]);
    const float corr = tm[tid >> 4] - M;     // this thread's 8 elems share a tile

    uint4 pk = *(const uint4*)(Sh + row * (size_t)SEQ + tid * 8);
    __half2* hp = (__half2*)&pk;
    float v[8];
    #pragma unroll
    for (int i = 0; i < 4; i++) {
        float2 f = __half22float2(hp[i]);
        v[2*i]   = __expf(f.x + corr);
        v[2*i+1] = __expf(f.y + corr);
    }
    float s = 0.f;
    #pragma unroll
    for (int i = 0; i < 8; i++) s += v[i];
    #pragma unroll
    for (int o = 16; o > 0; o >>= 1) s += __shfl_xor_sync(~0u, s, o);
    if ((tid & 31) == 0) red_sum[tid >> 5] = s;
    __syncthreads();
    if (tid < 32) {
        float t = (tid < 8) ? red_sum[tid] : 0.f;
        #pragma unroll
        for (int o = 4; o > 0; o >>= 1) t += __shfl_xor_sync(~0u, t, o);
        if (tid == 0) red_sum[0] = t;
    }
    __syncthreads();
    const float inv = 1.f / red_sum[0];
    __half2 ov[4];
    #pragma unroll
    for (int i = 0; i < 4; i++) {
        ov[i] = mkh2(__float2half_rn(v[2*i] * inv), __float2half_rn(v[2*i+1] * inv));
    }
    *(uint4*)(Ph + row * (size_t)SEQ + tid * 8) = *(uint4*)ov;
}

// ===========================================================================
extern "C" void kernel_launch(void* const* d_in, const int* in_sizes, int n_in,
                              void* d_out, int out_size) {
    const float* x  = (const float*)d_in[0];
    const float* Wq = (const float*)d_in[1];
    const float* bq = (const float*)d_in[2];
    const float* Wk = (const float*)d_in[3];
    const float* bk = (const float*)d_in[4];
    const float* Wm = (const float*)d_in[5];
    const float* bm = (const float*)d_in[6];
    float* out = (float*)d_out;

    __half* Sh; float* tmax;
    __half *xh, *Wqh, *Wql, *Wkh, *Wkl, *Wmh, *Wml;
    __half *Qh, *Ql, *Kh, *Ph, *ATTh;
    cudaGetSymbolAddress((void**)&Sh,   g_Sh);
    cudaGetSymbolAddress((void**)&tmax, g_tmax);
    cudaGetSymbolAddress((void**)&xh,   g_xh);
    cudaGetSymbolAddress((void**)&Wqh,  g_Wqh);  cudaGetSymbolAddress((void**)&Wql,  g_Wql);
    cudaGetSymbolAddress((void**)&Wkh,  g_Wkh);  cudaGetSymbolAddress((void**)&Wkl,  g_Wkl);
    cudaGetSymbolAddress((void**)&Wmh,  g_Wmh);  cudaGetSymbolAddress((void**)&Wml,  g_Wml);
    cudaGetSymbolAddress((void**)&Qh,   g_Qh);   cudaGetSymbolAddress((void**)&Ql,   g_Ql);
    cudaGetSymbolAddress((void**)&Kh,   g_Kh);
    cudaGetSymbolAddress((void**)&Ph,   g_Ph);
    cudaGetSymbolAddress((void**)&ATTh, g_ATTh);

    static int attr_done = 0;
    if (!attr_done) {
        cudaFuncSetAttribute(gemm_s_tc,   cudaFuncAttributeMaxDynamicSharedMemorySize, SMEM_2S_BYTES);
        cudaFuncSetAttribute(gemm_att_tc, cudaFuncAttributeMaxDynamicSharedMemorySize, SMEM_ATT_BYTES);
        cudaFuncSetAttribute(gemm_qk_tc,  cudaFuncAttributeMaxDynamicSharedMemorySize, SMEM_2S_BYTES);
        cudaFuncSetAttribute(gemm_out_tc, cudaFuncAttributeMaxDynamicSharedMemorySize, SMEM_2S_BYTES);
        attr_done = 1;
    }

    const dim3 blk(256);

    // preconvert x (hi) + weights (hi/lo)
    const int total4 = NX4 + 3 * W4;
    split_all<<<(total4 + 255) / 256, blk>>>(x, Wq, Wk, Wm, xh,
                                             Wqh, Wql, Wkh, Wkl, Wmh, Wml);

    // q+k projections
    const dim3 gqk(CH / 128, MTOT / 128, 2);
    gemm_qk_tc<<<gqk, blk, SMEM_2S_BYTES>>>(xh, Wqh, Wql, Wkh, Wkl,
                                            bq, bk, Qh, Ql, Kh);

    // S = K_hi @ (Q_hi + Q_lo)^T  -> fp16 (s - tilemax) + tilemax
    const dim3 g2(SEQ / 128, SEQ / 128, Bsz);
    gemm_s_tc<<<g2, blk, SMEM_2S_BYTES>>>(Kh, Qh, Ql, Sh, tmax);

    // softmax -> P (fp16)
    softmax_f16<<<Bsz * SEQ, blk>>>(Sh, tmax, Ph);

    // ATT = P_hi @ V_hi  (V = Q_hi)
    const dim3 g3(SEQ / 128, CH / 128, Bsz);
    gemm_att_tc<<<g3, blk, SMEM_ATT_BYTES>>>(Ph, Qh, ATTh);

    // out = relu(ATT_hi @ (Wm_hi + Wm_lo) + bm)
    const dim3 g1(CH / 128, MTOT / 128);
    gemm_out_tc<<<g1, blk, SMEM_2S_BYTES>>>(ATTh, Wmh, Wml, bm, out);
}